// round 12
// baseline (speedup 1.0000x reference)
#include <cuda_runtime.h>
#include <cuda_bf16.h>
#include <cuda_fp16.h>
#include <cstdint>

#define BT_   8192
#define IN_   4096
#define OUT_  4096
#define R_    64
#define T_    8

// ---------------- device scratch ----------------
__device__ float          g_W1[T_ * R_ * R_];
__device__ __half         g_Bth[T_ * R_ * IN_];    // Bt = in_core@W1 : fp16 [t][n][k]
__device__ __half         g_och[OUT_ * R_];        // out_core fp16 [n][k]
__device__ __half         g_vhi[BT_ * R_];         // v fp16

typedef unsigned long long u64;

// ---------- packed f32x2 ----------
__device__ __forceinline__ u64 pk2(float lo, float hi) {
    u64 r; asm("mov.b64 %0, {%1, %2};" : "=l"(r) : "f"(lo), "f"(hi)); return r;
}
__device__ __forceinline__ void upk2(u64 v, float& lo, float& hi) {
    asm("mov.b64 {%0, %1}, %2;" : "=f"(lo), "=f"(hi) : "l"(v));
}
__device__ __forceinline__ u64 ffma2(u64 a, u64 b, u64 c) {
    u64 d; asm("fma.rn.f32x2 %0, %1, %2, %3;" : "=l"(d) : "l"(a), "l"(b), "l"(c)); return d;
}

// ---------- tensor-core primitives (base-ISA, sm_103-safe) ----------
__device__ __forceinline__ void mma16816h(float* c, uint32_t a0, uint32_t a1,
                                          uint32_t a2, uint32_t a3,
                                          uint32_t b0, uint32_t b1) {
    asm volatile(
        "mma.sync.aligned.m16n8k16.row.col.f32.f16.f16.f32 "
        "{%0,%1,%2,%3}, {%4,%5,%6,%7}, {%8,%9}, {%0,%1,%2,%3};"
        : "+f"(c[0]), "+f"(c[1]), "+f"(c[2]), "+f"(c[3])
        : "r"(a0), "r"(a1), "r"(a2), "r"(a3), "r"(b0), "r"(b1));
}
__device__ __forceinline__ void ldsm4(uint32_t* r, uint32_t saddr) {
    asm volatile("ldmatrix.sync.aligned.m8n8.x4.shared.b16 {%0,%1,%2,%3}, [%4];"
                 : "=r"(r[0]), "=r"(r[1]), "=r"(r[2]), "=r"(r[3]) : "r"(saddr));
}
__device__ __forceinline__ void cpa16(uint32_t dst, const void* src) {
    asm volatile("cp.async.cg.shared.global [%0], [%1], 16;" :: "r"(dst), "l"(src));
}
#define CP_COMMIT() asm volatile("cp.async.commit_group;" ::: "memory")
#define CP_WAIT0()  asm volatile("cp.async.wait_group 0;" ::: "memory")

__device__ __forceinline__ uint32_t smem_u32(const void* p) {
    uint32_t a;
    asm("{ .reg .u64 t; cvta.to.shared.u64 t, %1; cvt.u32.u64 %0, t; }" : "=r"(a) : "l"(p));
    return a;
}

// row stride in all smem tile matrices: 144 bytes (36 words) -> LDSM conflict-free
#define RSTR 144

// ---------------------------------------------------------------------------
// k_pre1: out_core fp16 (bx<64) + W1 (bx in [64,192)).
// ---------------------------------------------------------------------------
__global__ __launch_bounds__(256) void k_pre1(const float* __restrict__ task,
                                              const float* __restrict__ tc,
                                              const float* __restrict__ out_core) {
    const int bx = blockIdx.x, tid = threadIdx.x;
    if (bx < 64) {
        const size_t base = (size_t)bx * 4096 + (size_t)tid * 16;
#pragma unroll
        for (int j = 0; j < 16; j += 4) {
            float4 v = *(const float4*)&out_core[base + j];
            __half2 h0 = __floats2half2_rn(v.x, v.y);
            __half2 h1 = __floats2half2_rn(v.z, v.w);
            *(uint32_t*)&g_och[base + j]     = *(uint32_t*)&h0;
            *(uint32_t*)&g_och[base + j + 2] = *(uint32_t*)&h1;
        }
    } else {
        const int idx = (bx - 64) * 256 + tid;
        const int t = idx >> 12, kl = idx & 4095;
        float a0 = 0, a1 = 0, a2 = 0, a3 = 0;
#pragma unroll
        for (int j = 0; j < 64; j += 4) {
            a0 += task[t * 64 + j + 0] * tc[(size_t)(j + 0) * 4096 + kl];
            a1 += task[t * 64 + j + 1] * tc[(size_t)(j + 1) * 4096 + kl];
            a2 += task[t * 64 + j + 2] * tc[(size_t)(j + 2) * 4096 + kl];
            a3 += task[t * 64 + j + 3] * tc[(size_t)(j + 3) * 4096 + kl];
        }
        g_W1[idx] = (a0 + a1) + (a2 + a3);
    }
}

// ---------------------------------------------------------------------------
// k_bt: Bt[t][k][n] = sum_j in_core[k][j]*W1[t][j][n] -> fp16 [t][n][k].
// ---------------------------------------------------------------------------
__global__ __launch_bounds__(256) void k_bt(const float* __restrict__ in_core) {
    __shared__ float W1s[4096];
    const int bx = blockIdx.x, tid = threadIdx.x;
    const int t = bx >> 4;
    const int row = (bx & 15) * 256 + tid;      // k index
    {
        const float4* src = (const float4*)(g_W1 + t * 4096);
        float4* dst = (float4*)W1s;
#pragma unroll
        for (int i = 0; i < 4; i++) dst[tid + i * 256] = src[tid + i * 256];
    }
    __syncthreads();

    u64 acc[32];
#pragma unroll
    for (int i = 0; i < 32; i++) acc[i] = 0ull;

    const float* icr = in_core + (size_t)row * 64;
#pragma unroll
    for (int jc = 0; jc < 4; jc++) {
        float4 a4[4];
#pragma unroll
        for (int q = 0; q < 4; q++) a4[q] = *(const float4*)(icr + jc * 16 + q * 4);
#pragma unroll
        for (int jj = 0; jj < 16; jj++) {
            const int j = jc * 16 + jj;
            float a = ((const float*)a4)[jj];
            u64 a2 = pk2(a, a);
#pragma unroll
            for (int i2 = 0; i2 < 16; i2++) {
                ulonglong2 w = *(const ulonglong2*)&W1s[j * 64 + i2 * 4];
                acc[2 * i2]     = ffma2(a2, w.x, acc[2 * i2]);
                acc[2 * i2 + 1] = ffma2(a2, w.y, acc[2 * i2 + 1]);
            }
        }
    }
    // fp16 round + transposed store: Bt[t][n][row]
#pragma unroll
    for (int i = 0; i < 32; i++) {
        float v0, v1;
        upk2(acc[i], v0, v1);
        const size_t b0 = ((size_t)t * 64 + 2 * i) * IN_ + row;
        const size_t b1 = ((size_t)t * 64 + 2 * i + 1) * IN_ + row;
        g_Bth[b0] = __float2half(v0);
        g_Bth[b1] = __float2half(v1);
    }
}

// ---------------------------------------------------------------------------
// k_gemm1: v = x @ Bt[t]  (tile 32m x 64n, FULL K=4096 = 64 chunks of 64).
// 256 CTAs: t = bx&7, g = bx>>3 (g<32); rows = t + 8*(g*32 + r), r=0..31.
// fp16 single-term, direct fp16 v output (no split-K, no reduction kernel).
// Warp grid 2m x 4n, warp tile 16x16.  3 CTAs/SM.
// smem/stage 13824B: A@0 (32 x 144), B@4608 (64 x 144);  2 stages = 27648B.
// ---------------------------------------------------------------------------
#define G1_STG  13824
#define G1_SMEM 27648

__global__ __launch_bounds__(256, 3) void k_gemm1(const float* __restrict__ x) {
    extern __shared__ char sm[];
    const uint32_t sb = smem_u32(sm);
    const int tid = threadIdx.x, warp = tid >> 5, lane = tid & 31;
    const int gr = lane >> 2, p = lane & 3;
    const int bx = blockIdx.x;
    const int t = bx & 7, g = bx >> 3;

    // x loader mapping: 8 threads per row (32 rows)
    const int lrow = tid >> 3, lq = tid & 7;
    const float* xrp = x + (size_t)(t + 8 * (g * 32 + lrow)) * IN_ + lq * 4;

    // B cp.async mapping: 4 threads per row (64 rows)
    const int bn = tid >> 2, bj = tid & 3;
    const __half* bth = g_Bth + ((size_t)t * 64 + bn) * IN_;
    const uint32_t dB = sb + 4608 + bn * RSTR;

    // ldmatrix lane roles
    const int m0 = (warp >> 2) * 16, n0 = (warp & 3) * 16;
    const int lr = (lane & 7) + ((lane >> 3) & 1) * 8;
    const int lk = (lane >> 4) * 16;
    const uint32_t offA = (uint32_t)((m0 + lr) * RSTR + lk);
    const uint32_t offB = (uint32_t)(4608 + (n0 + lr) * RSTR + lk);

    float acc[2][4];
#pragma unroll
    for (int i = 0; i < 2; i++) acc[i][0] = acc[i][1] = acc[i][2] = acc[i][3] = 0.f;

    float4 xv[2];

#define G1_BLOAD(st_, c_) do {                                                \
    const uint32_t d = dB + (st_) * G1_STG;                                   \
    cpa16(d + bj * 16,        bth + (c_) * 64 + bj * 8);                      \
    cpa16(d + (bj + 4) * 16,  bth + (c_) * 64 + (bj + 4) * 8);                \
} while (0)

#define G1_XLDG(c_) do {                                                      \
    const float* srcx = xrp + (c_) * 64;                                      \
    xv[0] = *(const float4*)(srcx);                                           \
    xv[1] = *(const float4*)(srcx + 32);                                      \
} while (0)

#define G1_XSTS(st_) do {                                                     \
    char* ah = sm + (st_) * G1_STG + lrow * RSTR + lq * 8;                    \
    _Pragma("unroll")                                                         \
    for (int seg = 0; seg < 2; seg++) {                                       \
        __half2 h0 = __floats2half2_rn(xv[seg].x, xv[seg].y);                 \
        __half2 h1 = __floats2half2_rn(xv[seg].z, xv[seg].w);                 \
        *(uint2*)(ah + seg * 64) = make_uint2(*(uint32_t*)&h0, *(uint32_t*)&h1); \
    }                                                                         \
} while (0)

    // prologue: chunk 0 -> stage 0
    G1_BLOAD(0, 0);
    CP_COMMIT();
    G1_XLDG(0);
    G1_XSTS(0);

    for (int c = 0; c < 64; c++) {
        const int s = c & 1;
        CP_WAIT0();
        __syncthreads();
        if (c < 63) {
            G1_BLOAD(s ^ 1, c + 1);
            CP_COMMIT();
            G1_XLDG(c + 1);          // LDG in flight during compute below
        }
        // compute chunk c from stage s
        const uint32_t st = sb + s * G1_STG;
#pragma unroll
        for (int ks = 0; ks < 4; ks++) {
            const uint32_t ka = ks * 32;
            uint32_t A[4], B[4];
            ldsm4(A, st + offA + ka);
            ldsm4(B, st + offB + ka);
            mma16816h(acc[0], A[0], A[1], A[2], A[3], B[0], B[2]);
            mma16816h(acc[1], A[0], A[1], A[2], A[3], B[1], B[3]);
        }
        if (c < 63) G1_XSTS(s ^ 1);   // cvt + store AFTER compute (LDG hidden)
    }

    // direct fp16 v store: warp tile 16x16 at (m0, n0)
    const size_t r0 = (size_t)(t + 8 * (g * 32 + m0 + gr));
    const size_t r1 = r0 + 64;   // row + 8 in tile = +64 global
#pragma unroll
    for (int nt = 0; nt < 2; nt++) {
        const int col = n0 + nt * 8 + 2 * p;
        __half2 v0 = __floats2half2_rn(acc[nt][0], acc[nt][1]);
        __half2 v1 = __floats2half2_rn(acc[nt][2], acc[nt][3]);
        *(uint32_t*)&g_vhi[r0 * 64 + col] = *(uint32_t*)&v0;
        *(uint32_t*)&g_vhi[r1 * 64 + col] = *(uint32_t*)&v1;
    }
}

// ---------------------------------------------------------------------------
// k_gemm2: y = v @ och^T (fp16 single-term).  Tile 128x128, K=64,
// warp tile 64x32.  smem: AH@0 BH@18432 = 36864B.  grid (32, 64).
// ---------------------------------------------------------------------------
#define G2_SMEM 36864

__global__ __launch_bounds__(256, 2) void k_gemm2(float* __restrict__ y) {
    extern __shared__ char sm[];
    const uint32_t sb = smem_u32(sm);
    const int tid = threadIdx.x, warp = tid >> 5, lane = tid & 31;
    const int gr = lane >> 2, p = lane & 3;
    const int n0b = blockIdx.x * 128, m0b = blockIdx.y * 128;

    {   // cp.async both tiles
        const int row = tid >> 1, q = (tid & 1) * 4;
        const uint32_t drow = sb + row * RSTR;
        const __half* sa  = g_vhi + (size_t)(m0b + row) * 64;
        const __half* sbh = g_och + (size_t)(n0b + row) * 64;
#pragma unroll
        for (int j = 0; j < 4; j++) {
            cpa16(drow + (q + j) * 16,         sa  + (q + j) * 8);
            cpa16(drow + 18432 + (q + j) * 16, sbh + (q + j) * 8);
        }
    }
    CP_COMMIT();
    CP_WAIT0();
    __syncthreads();

    const int m0 = (warp >> 2) * 64, n0 = (warp & 3) * 32;
    const int lr = (lane & 7) + ((lane >> 3) & 1) * 8;
    const int lk = (lane >> 4) * 16;
    const uint32_t offA = (uint32_t)((m0 + lr) * RSTR + lk);
    const uint32_t offB = (uint32_t)((n0 + lr) * RSTR + lk);

    float acc[4][4][4];
#pragma unroll
    for (int mt = 0; mt < 4; mt++)
#pragma unroll
        for (int nt = 0; nt < 4; nt++)
            acc[mt][nt][0] = acc[mt][nt][1] = acc[mt][nt][2] = acc[mt][nt][3] = 0.f;

#pragma unroll
    for (int ks = 0; ks < 4; ks++) {
        const uint32_t ka = ks * 32;
        uint32_t Ah[4][4], B0[4], B1[4];
#pragma unroll
        for (int mt = 0; mt < 4; mt++)
            ldsm4(Ah[mt], sb + offA + mt * 16 * RSTR + ka);
        ldsm4(B0, sb + 18432 + offB + ka);
        ldsm4(B1, sb + 18432 + 16 * RSTR + offB + ka);
#pragma unroll
        for (int mt = 0; mt < 4; mt++) {
            mma16816h(acc[mt][0], Ah[mt][0], Ah[mt][1], Ah[mt][2], Ah[mt][3], B0[0], B0[2]);
            mma16816h(acc[mt][1], Ah[mt][0], Ah[mt][1], Ah[mt][2], Ah[mt][3], B0[1], B0[3]);
            mma16816h(acc[mt][2], Ah[mt][0], Ah[mt][1], Ah[mt][2], Ah[mt][3], B1[0], B1[2]);
            mma16816h(acc[mt][3], Ah[mt][0], Ah[mt][1], Ah[mt][2], Ah[mt][3], B1[1], B1[3]);
        }
    }

#pragma unroll
    for (int mt = 0; mt < 4; mt++) {
#pragma unroll
        for (int nt = 0; nt < 4; nt++) {
            const int row = m0b + m0 + mt * 16 + gr;
            const int col = n0b + n0 + nt * 8 + 2 * p;
            *(float2*)&y[(size_t)row * OUT_ + col] =
                make_float2(acc[mt][nt][0], acc[mt][nt][1]);
            *(float2*)&y[(size_t)(row + 8) * OUT_ + col] =
                make_float2(acc[mt][nt][2], acc[mt][nt][3]);
        }
    }
}

// ---------------------------------------------------------------------------
extern "C" void kernel_launch(void* const* d_in, const int* in_sizes, int n_in,
                              void* d_out, int out_size) {
    const float* x        = (const float*)d_in[0];
    const float* tc       = (const float*)d_in[1];
    const float* task     = (const float*)d_in[2];
    const float* in_core  = (const float*)d_in[3];
    const float* out_core = (const float*)d_in[4];
    float* y = (float*)d_out;

    cudaFuncSetAttribute(k_gemm1, cudaFuncAttributeMaxDynamicSharedMemorySize, G1_SMEM);
    cudaFuncSetAttribute(k_gemm2, cudaFuncAttributeMaxDynamicSharedMemorySize, G2_SMEM);

    k_pre1<<<192, 256>>>(task, tc, out_core);
    k_bt<<<128, 256>>>(in_core);
    k_gemm1<<<256, 256, G1_SMEM>>>(x);
    k_gemm2<<<dim3(OUT_ / 128, BT_ / 128), 256, G2_SMEM>>>(y);
}

// round 13
// speedup vs baseline: 1.1469x; 1.1469x over previous
#include <cuda_runtime.h>
#include <cuda_bf16.h>
#include <cuda_fp16.h>
#include <cstdint>

#define BT_   8192
#define IN_   4096
#define OUT_  4096
#define R_    64
#define T_    8

// ---------------- device scratch ----------------
__device__ float          g_W1[T_ * R_ * R_];
__device__ __half         g_Bth[T_ * R_ * IN_];    // Bt = in_core@W1 : fp16 [t][n][k]
__device__ __half         g_och[OUT_ * R_];        // out_core fp16 [n][k]
__device__ float          g_vpart[2][BT_ * R_];    // split-K partials of v
__device__ __half         g_vhi[BT_ * R_];         // v fp16

typedef unsigned long long u64;

// ---------- packed f32x2 ----------
__device__ __forceinline__ u64 pk2(float lo, float hi) {
    u64 r; asm("mov.b64 %0, {%1, %2};" : "=l"(r) : "f"(lo), "f"(hi)); return r;
}
__device__ __forceinline__ void upk2(u64 v, float& lo, float& hi) {
    asm("mov.b64 {%0, %1}, %2;" : "=f"(lo), "=f"(hi) : "l"(v));
}
__device__ __forceinline__ u64 ffma2(u64 a, u64 b, u64 c) {
    u64 d; asm("fma.rn.f32x2 %0, %1, %2, %3;" : "=l"(d) : "l"(a), "l"(b), "l"(c)); return d;
}

// ---------- tensor-core primitives (base-ISA, sm_103-safe) ----------
__device__ __forceinline__ void mma16816h(float* c, uint32_t a0, uint32_t a1,
                                          uint32_t a2, uint32_t a3,
                                          uint32_t b0, uint32_t b1) {
    asm volatile(
        "mma.sync.aligned.m16n8k16.row.col.f32.f16.f16.f32 "
        "{%0,%1,%2,%3}, {%4,%5,%6,%7}, {%8,%9}, {%0,%1,%2,%3};"
        : "+f"(c[0]), "+f"(c[1]), "+f"(c[2]), "+f"(c[3])
        : "r"(a0), "r"(a1), "r"(a2), "r"(a3), "r"(b0), "r"(b1));
}
__device__ __forceinline__ void ldsm4(uint32_t* r, uint32_t saddr) {
    asm volatile("ldmatrix.sync.aligned.m8n8.x4.shared.b16 {%0,%1,%2,%3}, [%4];"
                 : "=r"(r[0]), "=r"(r[1]), "=r"(r[2]), "=r"(r[3]) : "r"(saddr));
}
__device__ __forceinline__ void cpa16(uint32_t dst, const void* src) {
    asm volatile("cp.async.cg.shared.global [%0], [%1], 16;" :: "r"(dst), "l"(src));
}
#define CP_COMMIT() asm volatile("cp.async.commit_group;" ::: "memory")
#define CP_WAIT0()  asm volatile("cp.async.wait_group 0;" ::: "memory")

__device__ __forceinline__ uint32_t smem_u32(const void* p) {
    uint32_t a;
    asm("{ .reg .u64 t; cvta.to.shared.u64 t, %1; cvt.u32.u64 %0, t; }" : "=r"(a) : "l"(p));
    return a;
}

// row stride in all smem tile matrices: 144 bytes (36 words) -> LDSM conflict-free
#define RSTR 144

// ---------------------------------------------------------------------------
// k_pre1: out_core fp16 (bx<64) + W1 (bx in [64,192)).
// ---------------------------------------------------------------------------
__global__ __launch_bounds__(256) void k_pre1(const float* __restrict__ task,
                                              const float* __restrict__ tc,
                                              const float* __restrict__ out_core) {
    const int bx = blockIdx.x, tid = threadIdx.x;
    if (bx < 64) {
        const size_t base = (size_t)bx * 4096 + (size_t)tid * 16;
#pragma unroll
        for (int j = 0; j < 16; j += 4) {
            float4 v = *(const float4*)&out_core[base + j];
            __half2 h0 = __floats2half2_rn(v.x, v.y);
            __half2 h1 = __floats2half2_rn(v.z, v.w);
            *(uint32_t*)&g_och[base + j]     = *(uint32_t*)&h0;
            *(uint32_t*)&g_och[base + j + 2] = *(uint32_t*)&h1;
        }
    } else {
        const int idx = (bx - 64) * 256 + tid;
        const int t = idx >> 12, kl = idx & 4095;
        float a0 = 0, a1 = 0, a2 = 0, a3 = 0;
#pragma unroll
        for (int j = 0; j < 64; j += 4) {
            a0 += task[t * 64 + j + 0] * tc[(size_t)(j + 0) * 4096 + kl];
            a1 += task[t * 64 + j + 1] * tc[(size_t)(j + 1) * 4096 + kl];
            a2 += task[t * 64 + j + 2] * tc[(size_t)(j + 2) * 4096 + kl];
            a3 += task[t * 64 + j + 3] * tc[(size_t)(j + 3) * 4096 + kl];
        }
        g_W1[idx] = (a0 + a1) + (a2 + a3);
    }
}

// ---------------------------------------------------------------------------
// k_bt: Bt[t][k][n] = sum_j in_core[k][j]*W1[t][j][n] -> fp16 [t][n][k].
// ---------------------------------------------------------------------------
__global__ __launch_bounds__(256) void k_bt(const float* __restrict__ in_core) {
    __shared__ float W1s[4096];
    const int bx = blockIdx.x, tid = threadIdx.x;
    const int t = bx >> 4;
    const int row = (bx & 15) * 256 + tid;      // k index
    {
        const float4* src = (const float4*)(g_W1 + t * 4096);
        float4* dst = (float4*)W1s;
#pragma unroll
        for (int i = 0; i < 4; i++) dst[tid + i * 256] = src[tid + i * 256];
    }
    __syncthreads();

    u64 acc[32];
#pragma unroll
    for (int i = 0; i < 32; i++) acc[i] = 0ull;

    const float* icr = in_core + (size_t)row * 64;
#pragma unroll
    for (int jc = 0; jc < 4; jc++) {
        float4 a4[4];
#pragma unroll
        for (int q = 0; q < 4; q++) a4[q] = *(const float4*)(icr + jc * 16 + q * 4);
#pragma unroll
        for (int jj = 0; jj < 16; jj++) {
            const int j = jc * 16 + jj;
            float a = ((const float*)a4)[jj];
            u64 a2 = pk2(a, a);
#pragma unroll
            for (int i2 = 0; i2 < 16; i2++) {
                ulonglong2 w = *(const ulonglong2*)&W1s[j * 64 + i2 * 4];
                acc[2 * i2]     = ffma2(a2, w.x, acc[2 * i2]);
                acc[2 * i2 + 1] = ffma2(a2, w.y, acc[2 * i2 + 1]);
            }
        }
    }
    // fp16 round + transposed store: Bt[t][n][row]
#pragma unroll
    for (int i = 0; i < 32; i++) {
        float v0, v1;
        upk2(acc[i], v0, v1);
        const size_t b0 = ((size_t)t * 64 + 2 * i) * IN_ + row;
        const size_t b1 = ((size_t)t * 64 + 2 * i + 1) * IN_ + row;
        g_Bth[b0] = __float2half(v0);
        g_Bth[b1] = __float2half(v1);
    }
}

// ---------------------------------------------------------------------------
// k_gemm1 (R11 config): v_partial = x @ Bt[t], tile 64m x 64n, K-slice 2048.
// 256 CTAs: mtile = bx>>1 (t = mtile&7, g = mtile>>3), kslice = bx&1.
// fp16 single-term.  smem/stage 18432B: A@0 B@9216;  2 stages = 36864B.
// ---------------------------------------------------------------------------
#define G1_STG  18432
#define G1_SMEM 36864

__global__ __launch_bounds__(256, 2) void k_gemm1(const float* __restrict__ x) {
    extern __shared__ char sm[];
    const uint32_t sb = smem_u32(sm);
    const int tid = threadIdx.x, warp = tid >> 5, lane = tid & 31;
    const int gr = lane >> 2, p = lane & 3;
    const int bx = blockIdx.x;
    const int mtile = bx >> 1, ksl = bx & 1;
    const int t = mtile & 7, g = mtile >> 3;
    const int koff = ksl * 2048;

    // x loader mapping: 4 threads per row
    const int lrow = tid >> 2, lq = tid & 3;
    const float* xrp = x + (size_t)(t + 8 * (g * 64 + lrow)) * IN_ + koff;

    // B cp.async mapping
    const int bn = tid >> 2, bj = tid & 3;
    const __half* bth = g_Bth + ((size_t)t * 64 + bn) * IN_ + koff;
    const uint32_t dB = sb + 9216 + bn * RSTR;

    // ldmatrix lane roles
    const int m0 = (warp >> 1) * 16, n0 = (warp & 1) * 32;
    const int lr = (lane & 7) + ((lane >> 3) & 1) * 8;
    const int lk = (lane >> 4) * 16;
    const uint32_t offA = (uint32_t)((m0 + lr) * RSTR + lk);
    const uint32_t offB = (uint32_t)((n0 + lr) * RSTR + lk);

    float acc[4][4];
#pragma unroll
    for (int i = 0; i < 4; i++) acc[i][0] = acc[i][1] = acc[i][2] = acc[i][3] = 0.f;

    float4 xv[4];

#define G1_BLOAD(st_, c_) do {                                                \
    const uint32_t d = dB + (st_) * G1_STG;                                   \
    cpa16(d + bj * 16,        bth + (c_) * 64 + bj * 8);                      \
    cpa16(d + (bj + 4) * 16,  bth + (c_) * 64 + (bj + 4) * 8);                \
} while (0)

#define G1_XLDG(c_) do {                                                      \
    const float* srcx = xrp + (c_) * 64;                                      \
    _Pragma("unroll")                                                         \
    for (int seg = 0; seg < 4; seg++)                                         \
        xv[seg] = *(const float4*)(srcx + seg * 16 + lq * 4);                 \
} while (0)

#define G1_XSTS(st_) do {                                                     \
    char* ah = sm + (st_) * G1_STG + lrow * RSTR + lq * 8;                    \
    _Pragma("unroll")                                                         \
    for (int seg = 0; seg < 4; seg++) {                                       \
        __half2 h0 = __floats2half2_rn(xv[seg].x, xv[seg].y);                 \
        __half2 h1 = __floats2half2_rn(xv[seg].z, xv[seg].w);                 \
        *(uint2*)(ah + seg * 32) = make_uint2(*(uint32_t*)&h0, *(uint32_t*)&h1); \
    }                                                                         \
} while (0)

    // prologue: chunk 0 -> stage 0
    G1_BLOAD(0, 0);
    CP_COMMIT();
    G1_XLDG(0);
    G1_XSTS(0);

    for (int c = 0; c < 32; c++) {
        const int s = c & 1;
        CP_WAIT0();
        __syncthreads();
        if (c < 31) {
            G1_BLOAD(s ^ 1, c + 1);
            CP_COMMIT();
            G1_XLDG(c + 1);          // LDG in flight during compute below
        }
        // compute chunk c from stage s
        const uint32_t st = sb + s * G1_STG;
#pragma unroll
        for (int ks = 0; ks < 4; ks++) {
            const uint32_t ka = ks * 32;
            uint32_t Ah[4], B0[4], B1[4];
            ldsm4(Ah, st + offA + ka);
            ldsm4(B0, st + 9216 + offB + ka);
            ldsm4(B1, st + 9216 + 16 * RSTR + offB + ka);
            mma16816h(acc[0], Ah[0], Ah[1], Ah[2], Ah[3], B0[0], B0[2]);
            mma16816h(acc[1], Ah[0], Ah[1], Ah[2], Ah[3], B0[1], B0[3]);
            mma16816h(acc[2], Ah[0], Ah[1], Ah[2], Ah[3], B1[0], B1[2]);
            mma16816h(acc[3], Ah[0], Ah[1], Ah[2], Ah[3], B1[1], B1[3]);
        }
        if (c < 31) G1_XSTS(s ^ 1);   // cvt + store AFTER compute (LDG hidden)
    }

    // store partials (deterministic plain stores)
    float* vp = g_vpart[ksl];
    const size_t r0 = (size_t)(t + 8 * (g * 64 + m0 + gr));
    const size_t r1 = r0 + 64;   // row + 8 in tile = +64 global
#pragma unroll
    for (int nt = 0; nt < 4; nt++) {
        const int col = n0 + nt * 8 + 2 * p;
        *(float2*)&vp[r0 * 64 + col] = make_float2(acc[nt][0], acc[nt][1]);
        *(float2*)&vp[r1 * 64 + col] = make_float2(acc[nt][2], acc[nt][3]);
    }
}

// ---------------------------------------------------------------------------
// k_vred: v = sum of 2 partials -> fp16.  512 blocks x 256 thr.
// ---------------------------------------------------------------------------
__global__ __launch_bounds__(256) void k_vred() {
    const int idx = blockIdx.x * 256 + threadIdx.x;   // float4 index
    const float4* p0 = (const float4*)g_vpart[0];
    const float4* p1 = (const float4*)g_vpart[1];
    float4 a = p0[idx], b = p1[idx];
    __half2 h0 = __floats2half2_rn(a.x + b.x, a.y + b.y);
    __half2 h1 = __floats2half2_rn(a.z + b.z, a.w + b.w);
    *(uint2*)&g_vhi[(size_t)idx * 4] = make_uint2(*(uint32_t*)&h0, *(uint32_t*)&h1);
}

// ---------------------------------------------------------------------------
// k_gemm2: y = v @ och^T (fp16 single-term).  Per CTA: one 128-row v tile
// (loaded once) x FOUR 128-col oc tiles, double-buffered cp.async across
// tiles.  Warp tile 64x32.  grid (8, 64) = 512 CTAs.
// smem: A@0 (128 x RSTR), B stages @18432 + s*18432;  total 55296B.
// ---------------------------------------------------------------------------
#define G2_STG  18432
#define G2_SMEM 55296

__global__ __launch_bounds__(256, 2) void k_gemm2(float* __restrict__ y) {
    extern __shared__ char sm[];
    const uint32_t sb = smem_u32(sm);
    const int tid = threadIdx.x, warp = tid >> 5, lane = tid & 31;
    const int gr = lane >> 2, p = lane & 3;
    const int nbase = blockIdx.x * 512, m0b = blockIdx.y * 128;

    // loader mapping: 2 threads per row
    const int row = tid >> 1, q = (tid & 1) * 4;
    const __half* sa = g_vhi + (size_t)(m0b + row) * 64;
    const __half* ob = g_och + (size_t)(nbase + row) * 64;
    const uint32_t dA = sb + row * RSTR;
    const uint32_t dB = sb + 18432 + row * RSTR;

#define G2_BLOAD(st_, i_) do {                                                \
    const uint32_t d = dB + (st_) * G2_STG;                                   \
    const __half* s_ = ob + (size_t)(i_) * 128 * 64;                          \
    _Pragma("unroll")                                                         \
    for (int j = 0; j < 4; j++) cpa16(d + (q + j) * 16, s_ + (q + j) * 8);    \
} while (0)

    // prologue: A tile + B tile 0
#pragma unroll
    for (int j = 0; j < 4; j++) cpa16(dA + (q + j) * 16, sa + (q + j) * 8);
    G2_BLOAD(0, 0);
    CP_COMMIT();

    const int m0 = (warp >> 2) * 64, n0 = (warp & 3) * 32;
    const int lr = (lane & 7) + ((lane >> 3) & 1) * 8;
    const int lk = (lane >> 4) * 16;
    const uint32_t offA = (uint32_t)((m0 + lr) * RSTR + lk);
    const uint32_t offB = (uint32_t)((n0 + lr) * RSTR + lk);

    for (int i = 0; i < 4; i++) {
        const int s = i & 1;
        CP_WAIT0();
        __syncthreads();
        if (i < 3) {
            G2_BLOAD(s ^ 1, i + 1);   // next oc tile in flight during compute
            CP_COMMIT();
        }
        const uint32_t stB = sb + 18432 + s * G2_STG;

        float acc[4][4][4];
#pragma unroll
        for (int mt = 0; mt < 4; mt++)
#pragma unroll
            for (int nt = 0; nt < 4; nt++)
                acc[mt][nt][0] = acc[mt][nt][1] = acc[mt][nt][2] = acc[mt][nt][3] = 0.f;

#pragma unroll
        for (int ks = 0; ks < 4; ks++) {
            const uint32_t ka = ks * 32;
            uint32_t Ah[4][4], B0[4], B1[4];
#pragma unroll
            for (int mt = 0; mt < 4; mt++)
                ldsm4(Ah[mt], sb + offA + mt * 16 * RSTR + ka);
            ldsm4(B0, stB + offB + ka);
            ldsm4(B1, stB + 16 * RSTR + offB + ka);
#pragma unroll
            for (int mt = 0; mt < 4; mt++) {
                mma16816h(acc[mt][0], Ah[mt][0], Ah[mt][1], Ah[mt][2], Ah[mt][3], B0[0], B0[2]);
                mma16816h(acc[mt][1], Ah[mt][0], Ah[mt][1], Ah[mt][2], Ah[mt][3], B0[1], B0[3]);
                mma16816h(acc[mt][2], Ah[mt][0], Ah[mt][1], Ah[mt][2], Ah[mt][3], B1[0], B1[2]);
                mma16816h(acc[mt][3], Ah[mt][0], Ah[mt][1], Ah[mt][2], Ah[mt][3], B1[1], B1[3]);
            }
        }

        const int n0b = nbase + i * 128;
#pragma unroll
        for (int mt = 0; mt < 4; mt++) {
#pragma unroll
            for (int nt = 0; nt < 4; nt++) {
                const int rrow = m0b + m0 + mt * 16 + gr;
                const int col = n0b + n0 + nt * 8 + 2 * p;
                *(float2*)&y[(size_t)rrow * OUT_ + col] =
                    make_float2(acc[mt][nt][0], acc[mt][nt][1]);
                *(float2*)&y[(size_t)(rrow + 8) * OUT_ + col] =
                    make_float2(acc[mt][nt][2], acc[mt][nt][3]);
            }
        }
    }
}

// ---------------------------------------------------------------------------
extern "C" void kernel_launch(void* const* d_in, const int* in_sizes, int n_in,
                              void* d_out, int out_size) {
    const float* x        = (const float*)d_in[0];
    const float* tc       = (const float*)d_in[1];
    const float* task     = (const float*)d_in[2];
    const float* in_core  = (const float*)d_in[3];
    const float* out_core = (const float*)d_in[4];
    float* y = (float*)d_out;

    cudaFuncSetAttribute(k_gemm1, cudaFuncAttributeMaxDynamicSharedMemorySize, G1_SMEM);
    cudaFuncSetAttribute(k_gemm2, cudaFuncAttributeMaxDynamicSharedMemorySize, G2_SMEM);

    k_pre1<<<192, 256>>>(task, tc, out_core);
    k_bt<<<128, 256>>>(in_core);
    k_gemm1<<<256, 256, G1_SMEM>>>(x);
    k_vred<<<512, 256>>>();
    k_gemm2<<<dim3(8, BT_ / 128), 256, G2_SMEM>>>(y);
}

// round 14
// speedup vs baseline: 1.1620x; 1.0132x over previous
#include <cuda_runtime.h>
#include <cuda_bf16.h>
#include <cuda_fp16.h>
#include <cstdint>

#define BT_   8192
#define IN_   4096
#define OUT_  4096
#define R_    64
#define T_    8

// ---------------- device scratch ----------------
__device__ float          g_W1[T_ * R_ * R_];
__device__ __half         g_Bth[T_ * R_ * IN_];    // Bt = in_core@W1 : fp16 [t][n][k]
__device__ __half         g_och[OUT_ * R_];        // out_core fp16 [n][k]
__device__ float          g_vpart[2][BT_ * R_];    // split-K partials of v

typedef unsigned long long u64;

// ---------- packed f32x2 ----------
__device__ __forceinline__ u64 pk2(float lo, float hi) {
    u64 r; asm("mov.b64 %0, {%1, %2};" : "=l"(r) : "f"(lo), "f"(hi)); return r;
}
__device__ __forceinline__ void upk2(u64 v, float& lo, float& hi) {
    asm("mov.b64 {%0, %1}, %2;" : "=f"(lo), "=f"(hi) : "l"(v));
}
__device__ __forceinline__ u64 ffma2(u64 a, u64 b, u64 c) {
    u64 d; asm("fma.rn.f32x2 %0, %1, %2, %3;" : "=l"(d) : "l"(a), "l"(b), "l"(c)); return d;
}

// ---------- tensor-core primitives (base-ISA, sm_103-safe) ----------
__device__ __forceinline__ void mma16816h(float* c, uint32_t a0, uint32_t a1,
                                          uint32_t a2, uint32_t a3,
                                          uint32_t b0, uint32_t b1) {
    asm volatile(
        "mma.sync.aligned.m16n8k16.row.col.f32.f16.f16.f32 "
        "{%0,%1,%2,%3}, {%4,%5,%6,%7}, {%8,%9}, {%0,%1,%2,%3};"
        : "+f"(c[0]), "+f"(c[1]), "+f"(c[2]), "+f"(c[3])
        : "r"(a0), "r"(a1), "r"(a2), "r"(a3), "r"(b0), "r"(b1));
}
__device__ __forceinline__ void ldsm4(uint32_t* r, uint32_t saddr) {
    asm volatile("ldmatrix.sync.aligned.m8n8.x4.shared.b16 {%0,%1,%2,%3}, [%4];"
                 : "=r"(r[0]), "=r"(r[1]), "=r"(r[2]), "=r"(r[3]) : "r"(saddr));
}
__device__ __forceinline__ void cpa16(uint32_t dst, const void* src) {
    asm volatile("cp.async.cg.shared.global [%0], [%1], 16;" :: "r"(dst), "l"(src));
}
#define CP_COMMIT() asm volatile("cp.async.commit_group;" ::: "memory")
#define CP_WAIT0()  asm volatile("cp.async.wait_group 0;" ::: "memory")

__device__ __forceinline__ uint32_t smem_u32(const void* p) {
    uint32_t a;
    asm("{ .reg .u64 t; cvta.to.shared.u64 t, %1; cvt.u32.u64 %0, t; }" : "=r"(a) : "l"(p));
    return a;
}

// row stride in all smem tile matrices: 144 bytes (36 words) -> LDSM conflict-free
#define RSTR 144

// ---------------------------------------------------------------------------
// k_pre1: out_core fp16 (bx<64) + W1 (bx in [64,192)).
// ---------------------------------------------------------------------------
__global__ __launch_bounds__(256) void k_pre1(const float* __restrict__ task,
                                              const float* __restrict__ tc,
                                              const float* __restrict__ out_core) {
    const int bx = blockIdx.x, tid = threadIdx.x;
    if (bx < 64) {
        const size_t base = (size_t)bx * 4096 + (size_t)tid * 16;
#pragma unroll
        for (int j = 0; j < 16; j += 4) {
            float4 v = *(const float4*)&out_core[base + j];
            __half2 h0 = __floats2half2_rn(v.x, v.y);
            __half2 h1 = __floats2half2_rn(v.z, v.w);
            *(uint32_t*)&g_och[base + j]     = *(uint32_t*)&h0;
            *(uint32_t*)&g_och[base + j + 2] = *(uint32_t*)&h1;
        }
    } else {
        const int idx = (bx - 64) * 256 + tid;
        const int t = idx >> 12, kl = idx & 4095;
        float a0 = 0, a1 = 0, a2 = 0, a3 = 0;
#pragma unroll
        for (int j = 0; j < 64; j += 4) {
            a0 += task[t * 64 + j + 0] * tc[(size_t)(j + 0) * 4096 + kl];
            a1 += task[t * 64 + j + 1] * tc[(size_t)(j + 1) * 4096 + kl];
            a2 += task[t * 64 + j + 2] * tc[(size_t)(j + 2) * 4096 + kl];
            a3 += task[t * 64 + j + 3] * tc[(size_t)(j + 3) * 4096 + kl];
        }
        g_W1[idx] = (a0 + a1) + (a2 + a3);
    }
}

// ---------------------------------------------------------------------------
// k_bt: Bt[t][k][n] = sum_j in_core[k][j]*W1[t][j][n] -> fp16 [t][n][k].
// ---------------------------------------------------------------------------
__global__ __launch_bounds__(256) void k_bt(const float* __restrict__ in_core) {
    __shared__ float W1s[4096];
    const int bx = blockIdx.x, tid = threadIdx.x;
    const int t = bx >> 4;
    const int row = (bx & 15) * 256 + tid;      // k index
    {
        const float4* src = (const float4*)(g_W1 + t * 4096);
        float4* dst = (float4*)W1s;
#pragma unroll
        for (int i = 0; i < 4; i++) dst[tid + i * 256] = src[tid + i * 256];
    }
    __syncthreads();

    u64 acc[32];
#pragma unroll
    for (int i = 0; i < 32; i++) acc[i] = 0ull;

    const float* icr = in_core + (size_t)row * 64;
#pragma unroll
    for (int jc = 0; jc < 4; jc++) {
        float4 a4[4];
#pragma unroll
        for (int q = 0; q < 4; q++) a4[q] = *(const float4*)(icr + jc * 16 + q * 4);
#pragma unroll
        for (int jj = 0; jj < 16; jj++) {
            const int j = jc * 16 + jj;
            float a = ((const float*)a4)[jj];
            u64 a2 = pk2(a, a);
#pragma unroll
            for (int i2 = 0; i2 < 16; i2++) {
                ulonglong2 w = *(const ulonglong2*)&W1s[j * 64 + i2 * 4];
                acc[2 * i2]     = ffma2(a2, w.x, acc[2 * i2]);
                acc[2 * i2 + 1] = ffma2(a2, w.y, acc[2 * i2 + 1]);
            }
        }
    }
    // fp16 round + transposed store: Bt[t][n][row]
#pragma unroll
    for (int i = 0; i < 32; i++) {
        float v0, v1;
        upk2(acc[i], v0, v1);
        const size_t b0 = ((size_t)t * 64 + 2 * i) * IN_ + row;
        const size_t b1 = ((size_t)t * 64 + 2 * i + 1) * IN_ + row;
        g_Bth[b0] = __float2half(v0);
        g_Bth[b1] = __float2half(v1);
    }
}

// ---------------------------------------------------------------------------
// k_gemm1 (R11 config): v_partial = x @ Bt[t], tile 64m x 64n, K-slice 2048.
// 256 CTAs: mtile = bx>>1 (t = mtile&7, g = mtile>>3), kslice = bx&1.
// fp16 single-term.  smem/stage 18432B: A@0 B@9216;  2 stages = 36864B.
// ---------------------------------------------------------------------------
#define G1_STG  18432
#define G1_SMEM 36864

__global__ __launch_bounds__(256, 2) void k_gemm1(const float* __restrict__ x) {
    extern __shared__ char sm[];
    const uint32_t sb = smem_u32(sm);
    const int tid = threadIdx.x, warp = tid >> 5, lane = tid & 31;
    const int gr = lane >> 2, p = lane & 3;
    const int bx = blockIdx.x;
    const int mtile = bx >> 1, ksl = bx & 1;
    const int t = mtile & 7, g = mtile >> 3;
    const int koff = ksl * 2048;

    // x loader mapping: 4 threads per row
    const int lrow = tid >> 2, lq = tid & 3;
    const float* xrp = x + (size_t)(t + 8 * (g * 64 + lrow)) * IN_ + koff;

    // B cp.async mapping
    const int bn = tid >> 2, bj = tid & 3;
    const __half* bth = g_Bth + ((size_t)t * 64 + bn) * IN_ + koff;
    const uint32_t dB = sb + 9216 + bn * RSTR;

    // ldmatrix lane roles
    const int m0 = (warp >> 1) * 16, n0 = (warp & 1) * 32;
    const int lr = (lane & 7) + ((lane >> 3) & 1) * 8;
    const int lk = (lane >> 4) * 16;
    const uint32_t offA = (uint32_t)((m0 + lr) * RSTR + lk);
    const uint32_t offB = (uint32_t)((n0 + lr) * RSTR + lk);

    float acc[4][4];
#pragma unroll
    for (int i = 0; i < 4; i++) acc[i][0] = acc[i][1] = acc[i][2] = acc[i][3] = 0.f;

    float4 xv[4];

#define G1_BLOAD(st_, c_) do {                                                \
    const uint32_t d = dB + (st_) * G1_STG;                                   \
    cpa16(d + bj * 16,        bth + (c_) * 64 + bj * 8);                      \
    cpa16(d + (bj + 4) * 16,  bth + (c_) * 64 + (bj + 4) * 8);                \
} while (0)

#define G1_XLDG(c_) do {                                                      \
    const float* srcx = xrp + (c_) * 64;                                      \
    _Pragma("unroll")                                                         \
    for (int seg = 0; seg < 4; seg++)                                         \
        xv[seg] = *(const float4*)(srcx + seg * 16 + lq * 4);                 \
} while (0)

#define G1_XSTS(st_) do {                                                     \
    char* ah = sm + (st_) * G1_STG + lrow * RSTR + lq * 8;                    \
    _Pragma("unroll")                                                         \
    for (int seg = 0; seg < 4; seg++) {                                       \
        __half2 h0 = __floats2half2_rn(xv[seg].x, xv[seg].y);                 \
        __half2 h1 = __floats2half2_rn(xv[seg].z, xv[seg].w);                 \
        *(uint2*)(ah + seg * 32) = make_uint2(*(uint32_t*)&h0, *(uint32_t*)&h1); \
    }                                                                         \
} while (0)

    // prologue: chunk 0 -> stage 0
    G1_BLOAD(0, 0);
    CP_COMMIT();
    G1_XLDG(0);
    G1_XSTS(0);

    for (int c = 0; c < 32; c++) {
        const int s = c & 1;
        CP_WAIT0();
        __syncthreads();
        if (c < 31) {
            G1_BLOAD(s ^ 1, c + 1);
            CP_COMMIT();
            G1_XLDG(c + 1);          // LDG in flight during compute below
        }
        // compute chunk c from stage s
        const uint32_t st = sb + s * G1_STG;
#pragma unroll
        for (int ks = 0; ks < 4; ks++) {
            const uint32_t ka = ks * 32;
            uint32_t Ah[4], B0[4], B1[4];
            ldsm4(Ah, st + offA + ka);
            ldsm4(B0, st + 9216 + offB + ka);
            ldsm4(B1, st + 9216 + 16 * RSTR + offB + ka);
            mma16816h(acc[0], Ah[0], Ah[1], Ah[2], Ah[3], B0[0], B0[2]);
            mma16816h(acc[1], Ah[0], Ah[1], Ah[2], Ah[3], B0[1], B0[3]);
            mma16816h(acc[2], Ah[0], Ah[1], Ah[2], Ah[3], B1[0], B1[2]);
            mma16816h(acc[3], Ah[0], Ah[1], Ah[2], Ah[3], B1[1], B1[3]);
        }
        if (c < 31) G1_XSTS(s ^ 1);   // cvt + store AFTER compute (LDG hidden)
    }

    // store partials (deterministic plain stores)
    float* vp = g_vpart[ksl];
    const size_t r0 = (size_t)(t + 8 * (g * 64 + m0 + gr));
    const size_t r1 = r0 + 64;   // row + 8 in tile = +64 global
#pragma unroll
    for (int nt = 0; nt < 4; nt++) {
        const int col = n0 + nt * 8 + 2 * p;
        *(float2*)&vp[r0 * 64 + col] = make_float2(acc[nt][0], acc[nt][1]);
        *(float2*)&vp[r1 * 64 + col] = make_float2(acc[nt][2], acc[nt][3]);
    }
}

// ---------------------------------------------------------------------------
// k_gemm2: y = v @ och^T (fp16 single-term).  Per CTA: one 128-row v tile
// (built inline from the two fp32 split-K partials — no vred kernel) x
// EIGHT 128-col oc tiles, double-buffered cp.async across tiles.
// Warp tile 64x32.  grid (4, 64) = 256 CTAs -> single wave at 2 CTAs/SM.
// smem: A@0 (128 x RSTR), B stages @18432 + s*18432;  total 55296B.
// ---------------------------------------------------------------------------
#define G2_STG  18432
#define G2_SMEM 55296

__global__ __launch_bounds__(256, 2) void k_gemm2(float* __restrict__ y) {
    extern __shared__ char sm[];
    const uint32_t sb = smem_u32(sm);
    const int tid = threadIdx.x, warp = tid >> 5, lane = tid & 31;
    const int gr = lane >> 2, p = lane & 3;
    const int nbase = blockIdx.x * 1024, m0b = blockIdx.y * 128;

    // loader mapping: 2 threads per row
    const int row = tid >> 1, q = (tid & 1) * 4;       // q: float4 index (B path)
    const __half* ob = g_och + (size_t)(nbase + row) * 64;
    const uint32_t dB = sb + 18432 + row * RSTR;

#define G2_BLOAD(st_, i_) do {                                                \
    const uint32_t d = dB + (st_) * G2_STG;                                   \
    const __half* s_ = ob + (size_t)(i_) * 128 * 64;                          \
    _Pragma("unroll")                                                         \
    for (int j = 0; j < 4; j++) cpa16(d + (q + j) * 16, s_ + (q + j) * 8);    \
} while (0)

    // prologue: B tile 0 via cp.async, then A tile inline (sum fp32 partials
    // -> fp16 -> smem) while the TMA-less cp.async is in flight.
    G2_BLOAD(0, 0);
    CP_COMMIT();
    {
        const int c0 = (tid & 1) * 32;                 // 32 floats per thread
        const float* p0 = g_vpart[0] + (size_t)(m0b + row) * 64 + c0;
        const float* p1 = g_vpart[1] + (size_t)(m0b + row) * 64 + c0;
        char* da = sm + row * RSTR + c0 * 2;
#pragma unroll
        for (int j = 0; j < 8; j++) {
            float4 a = *(const float4*)(p0 + j * 4);
            float4 b = *(const float4*)(p1 + j * 4);
            __half2 h0 = __floats2half2_rn(a.x + b.x, a.y + b.y);
            __half2 h1 = __floats2half2_rn(a.z + b.z, a.w + b.w);
            *(uint2*)(da + j * 8) = make_uint2(*(uint32_t*)&h0, *(uint32_t*)&h1);
        }
    }

    const int m0 = (warp >> 2) * 64, n0 = (warp & 3) * 32;
    const int lr = (lane & 7) + ((lane >> 3) & 1) * 8;
    const int lk = (lane >> 4) * 16;
    const uint32_t offA = (uint32_t)((m0 + lr) * RSTR + lk);
    const uint32_t offB = (uint32_t)((n0 + lr) * RSTR + lk);

    for (int i = 0; i < 8; i++) {
        const int s = i & 1;
        CP_WAIT0();
        __syncthreads();
        if (i < 7) {
            G2_BLOAD(s ^ 1, i + 1);   // next oc tile in flight during compute
            CP_COMMIT();
        }
        const uint32_t stB = sb + 18432 + s * G2_STG;

        float acc[4][4][4];
#pragma unroll
        for (int mt = 0; mt < 4; mt++)
#pragma unroll
            for (int nt = 0; nt < 4; nt++)
                acc[mt][nt][0] = acc[mt][nt][1] = acc[mt][nt][2] = acc[mt][nt][3] = 0.f;

#pragma unroll
        for (int ks = 0; ks < 4; ks++) {
            const uint32_t ka = ks * 32;
            uint32_t Ah[4][4], B0[4], B1[4];
#pragma unroll
            for (int mt = 0; mt < 4; mt++)
                ldsm4(Ah[mt], sb + offA + mt * 16 * RSTR + ka);
            ldsm4(B0, stB + offB + ka);
            ldsm4(B1, stB + 16 * RSTR + offB + ka);
#pragma unroll
            for (int mt = 0; mt < 4; mt++) {
                mma16816h(acc[mt][0], Ah[mt][0], Ah[mt][1], Ah[mt][2], Ah[mt][3], B0[0], B0[2]);
                mma16816h(acc[mt][1], Ah[mt][0], Ah[mt][1], Ah[mt][2], Ah[mt][3], B0[1], B0[3]);
                mma16816h(acc[mt][2], Ah[mt][0], Ah[mt][1], Ah[mt][2], Ah[mt][3], B1[0], B1[2]);
                mma16816h(acc[mt][3], Ah[mt][0], Ah[mt][1], Ah[mt][2], Ah[mt][3], B1[1], B1[3]);
            }
        }

        const int n0b = nbase + i * 128;
#pragma unroll
        for (int mt = 0; mt < 4; mt++) {
#pragma unroll
            for (int nt = 0; nt < 4; nt++) {
                const int rrow = m0b + m0 + mt * 16 + gr;
                const int col = n0b + n0 + nt * 8 + 2 * p;
                *(float2*)&y[(size_t)rrow * OUT_ + col] =
                    make_float2(acc[mt][nt][0], acc[mt][nt][1]);
                *(float2*)&y[(size_t)(rrow + 8) * OUT_ + col] =
                    make_float2(acc[mt][nt][2], acc[mt][nt][3]);
            }
        }
    }
}

// ---------------------------------------------------------------------------
extern "C" void kernel_launch(void* const* d_in, const int* in_sizes, int n_in,
                              void* d_out, int out_size) {
    const float* x        = (const float*)d_in[0];
    const float* tc       = (const float*)d_in[1];
    const float* task     = (const float*)d_in[2];
    const float* in_core  = (const float*)d_in[3];
    const float* out_core = (const float*)d_in[4];
    float* y = (float*)d_out;

    cudaFuncSetAttribute(k_gemm1, cudaFuncAttributeMaxDynamicSharedMemorySize, G1_SMEM);
    cudaFuncSetAttribute(k_gemm2, cudaFuncAttributeMaxDynamicSharedMemorySize, G2_SMEM);

    k_pre1<<<192, 256>>>(task, tc, out_core);
    k_bt<<<128, 256>>>(in_core);
    k_gemm1<<<256, 256, G1_SMEM>>>(x);
    k_gemm2<<<dim3(4, BT_ / 128), 256, G2_SMEM>>>(y);
}